// round 15
// baseline (speedup 1.0000x reference)
#include <cuda_runtime.h>
#include <cuda_fp16.h>
#include <cstdint>
#include <cstddef>
#include <math.h>

#define S_LEN   4096
#define D_MODEL 1024
#define NH      16
#define DKH     64
#define FF      4096

// ---------------- scratch (device globals: no allocation allowed) ----------
__device__ __half g_srch[S_LEN * D_MODEL];       // fp16 src
__device__ __half g_wqkv[3072 * D_MODEL];        // transposed [3072,1024] fp16 (Wq pre-scaled)
__device__ float  g_bqkv[3072];                  // bq pre-scaled
__device__ __half g_wo[D_MODEL * D_MODEL];       // transposed [N,K] fp16
__device__ __half g_w1[FF * D_MODEL];
__device__ __half g_w2[D_MODEL * FF];
__device__ __half g_qh[S_LEN * D_MODEL];         // Q fp16 [S,1024] (pre-scaled)
__device__ uint32_t g_kb[NH * S_LEN * 32];       // K fp16x2 [h][s][dk/2]
__device__ __half g_vt[NH * DKH * S_LEN];        // V^T fp16 [h][dk][s]
__device__ __half g_cch[S_LEN * D_MODEL];        // concat fp16
__device__ float  g_tmp[S_LEN * D_MODEL];
__device__ float  g_x1[S_LEN * D_MODEL];         // x1 fp32 (residual for LN2)
__device__ __half g_x1h[S_LEN * D_MODEL];        // x1 fp16 (FFN1 A)
__device__ __half g_h1h[S_LEN * FF];             // relu(ffn1) fp16 (FFN2 A)

#define QK_SCALE 0.18033688011112042591999058f    // 0.125 * log2(e)

// ---------------- helpers ---------------------------------------------------
__device__ __forceinline__ uint32_t packh(float lo, float hi) {
    uint32_t r;
    asm("cvt.rn.f16x2.f32 %0, %1, %2;" : "=r"(r) : "f"(hi), "f"(lo));
    return r;
}

__device__ __forceinline__ uint32_t ex2h2(uint32_t x) {
    uint32_t y;
    asm("ex2.approx.f16x2 %0, %1;" : "=r"(y) : "r"(x));
    return y;
}

__device__ __forceinline__ uint32_t smem_u32(const void* p) {
    uint32_t a;
    asm("{ .reg .u64 t; cvta.to.shared.u64 t, %1; cvt.u32.u64 %0, t; }"
        : "=r"(a) : "l"(p));
    return a;
}

// m16n8k16 fp16 HMMA, fp32 accum, D += A*B
__device__ __forceinline__ void mmaf16(float c[4], const uint32_t a[4],
                                       uint32_t b0, uint32_t b1) {
    asm volatile(
        "mma.sync.aligned.m16n8k16.row.col.f32.f16.f16.f32 "
        "{%0,%1,%2,%3}, {%4,%5,%6,%7}, {%8,%9}, {%0,%1,%2,%3};"
        : "+f"(c[0]), "+f"(c[1]), "+f"(c[2]), "+f"(c[3])
        : "r"(a[0]), "r"(a[1]), "r"(a[2]), "r"(a[3]), "r"(b0), "r"(b1));
}

#define LDSMX4(r, a) \
    asm volatile("ldmatrix.sync.aligned.m8n8.x4.shared.b16 {%0,%1,%2,%3}, [%4];" \
        : "=r"((r)[0]), "=r"((r)[1]), "=r"((r)[2]), "=r"((r)[3]) : "r"(a))

#define CPASYNC(dst, src) \
    asm volatile("cp.async.cg.shared.global [%0], [%1], 16;" :: "r"(dst), "l"(src))
#define CPCOMMIT() asm volatile("cp.async.commit_group;" ::: "memory")
#define CPWAIT(n)  asm volatile("cp.async.wait_group %0;" :: "n"(n) : "memory")

// ---------------- prep kernels (3 launches) ----------------------------------
__global__ void half_copy_bias(const float4* __restrict__ x, __half2* __restrict__ y,
                               int n4, const float* __restrict__ bq,
                               const float* __restrict__ bk,
                               const float* __restrict__ bv) {
    const int i = blockIdx.x * 256 + threadIdx.x;
    if (i < n4) {
        float4 v = x[i];
        y[2 * i]     = __floats2half2_rn(v.x, v.y);
        y[2 * i + 1] = __floats2half2_rn(v.z, v.w);
    }
    if (i < D_MODEL) {
        g_bqkv[i] = bq[i] * QK_SCALE;      // Q bias pre-scaled
        g_bqkv[i + 1024] = bk[i];
        g_bqkv[i + 2048] = bv[i];
    }
}

// fused transpose of Wo/W1/W2 (f32 [R][C] -> fp16 [C][R]), 1-D decoded grid
__global__ void transpose_all(const float* __restrict__ Wo,
                              const float* __restrict__ W1,
                              const float* __restrict__ W2) {
    __shared__ float t[32][33];
    int id = blockIdx.x;
    const float* src;
    __half* dst;
    int R, C, bx, by;
    if (id < 1024) {                       // Wo: 1024x1024
        src = Wo; dst = g_wo; R = D_MODEL; C = D_MODEL;
        bx = (id & 31) * 32; by = (id >> 5) * 32;
    } else if (id < 1024 + 4096) {         // W1: [1024,4096] -> [4096,1024]
        id -= 1024;
        src = W1; dst = g_w1; R = D_MODEL; C = FF;
        bx = (id & 127) * 32; by = (id >> 7) * 32;
    } else {                               // W2: [4096,1024] -> [1024,4096]
        id -= 1024 + 4096;
        src = W2; dst = g_w2; R = FF; C = D_MODEL;
        bx = (id & 31) * 32; by = (id >> 5) * 32;
    }
    const int tx = threadIdx.x, ty = threadIdx.y;
    {
        const int x = bx + tx;
#pragma unroll
        for (int j = 0; j < 32; j += 8)
            t[ty + j][tx] = src[(size_t)(by + ty + j) * C + x];
    }
    __syncthreads();
    {
        const int x = by + tx;
#pragma unroll
        for (int j = 0; j < 32; j += 8)
            dst[(size_t)(bx + ty + j) * R + x] = __float2half_rn(t[tx][ty + j]);
    }
}

// QKV weights [NH][1024][64] -> g_wqkv [3*NH*64][1024] fp16; Wq pre-scaled
__global__ void pack_qkvT3(const float* __restrict__ Wq, const float* __restrict__ Wk,
                           const float* __restrict__ Wv) {
    __shared__ float t[32][33];
    const int which = blockIdx.z >> 4;          // 0=q,1=k,2=v
    const int head = blockIdx.z & 15;
    const float* W = (which == 0) ? Wq : (which == 1) ? Wk : Wv;
    const float sc = (which == 0) ? (float)QK_SCALE : 1.0f;
    const float* s = W + (size_t)head * D_MODEL * DKH;
    __half* d = g_wqkv + ((size_t)which * 1024 + head * DKH) * D_MODEL;
    const int tx = threadIdx.x, ty = threadIdx.y;
    {
        const int x = blockIdx.x * 32 + tx;          // dk
#pragma unroll
        for (int j = 0; j < 32; j += 8)
            t[ty + j][tx] = s[(size_t)(blockIdx.y * 32 + ty + j) * DKH + x];
    }
    __syncthreads();
    {
        const int x = blockIdx.y * 32 + tx;          // d
#pragma unroll
        for (int j = 0; j < 32; j += 8)
            d[(size_t)(blockIdx.x * 32 + ty + j) * D_MODEL + x] =
                __float2half_rn(t[tx][ty + j] * sc);
    }
}

// ======================= FP16 GEMM (256 thr, ldmatrix, 3-stage) ==============
// C = A @ Bt^T + bias. A [M,K] half (lda), Bt [N,K] half (ldb).
// CTA 128x128, 256 threads, 8 warps 2(M)x4(N), warp tile 64x32, k-chunk 32.
// 3-stage / 61440 B smem + <=128 regs -> 2 CTAs/SM = 4 warps/SMSP.
// MODE 0: fp32 C.  MODE 1: QKV (Q fp16 pre-scaled / K fp16x2 / V^T fp16).
// MODE 2: half C (+ ReLU via RELU flag).
template <int MODE, bool RELU>
__global__ void __launch_bounds__(256, 2)
gemm_f16(const __half* __restrict__ A, const __half* __restrict__ Bt,
         const float* __restrict__ bias, void* __restrict__ C,
         int K, int lda, int ldb, int ldc)
{
    constexpr int ASB = 80;                      // bytes per smem row
    constexpr uint32_t STAGE = 128 * ASB;        // 10240 B
    extern __shared__ uint32_t dsm[];
    const uint32_t saA = smem_u32(dsm);
    const uint32_t saB = saA + 3 * STAGE;

    const int tid = threadIdx.x, lane = tid & 31, wid = tid >> 5;
    const int wm = wid & 1, wn = wid >> 1;       // 2(M) x 4(N)
    const int m0 = blockIdx.y * 128, n0 = blockIdx.x * 128;

    const __half* Ab = A + (size_t)m0 * lda;
    const __half* Bb = Bt + (size_t)n0 * ldb;

    float acc[4][4][4];
#pragma unroll
    for (int mt = 0; mt < 4; mt++)
#pragma unroll
        for (int nt = 0; nt < 4; nt++)
#pragma unroll
            for (int j = 0; j < 4; j++) acc[mt][nt][j] = 0.f;

    auto issue = [&](int ch) {
        const int st = ch % 3;
        const __half* Ac = Ab + ch * 32;
        const uint32_t ad = saA + st * STAGE;
#pragma unroll
        for (int i = 0; i < 2; i++) {
            const int idx = tid + i * 256;
            const int r = idx >> 2, q = idx & 3;
            CPASYNC(ad + r * ASB + q * 16, Ac + (size_t)r * lda + q * 8);
        }
        const __half* Bc = Bb + ch * 32;
        const uint32_t bd = saB + st * STAGE;
#pragma unroll
        for (int i = 0; i < 2; i++) {
            const int idx = tid + i * 256;
            const int r = idx >> 2, q = idx & 3;
            CPASYNC(bd + r * ASB + q * 16, Bc + (size_t)r * ldb + q * 8);
        }
    };

    auto compute = [&](int st) {
        const uint32_t aBase = saA + st * STAGE +
            (wm * 64 + (lane & 15)) * ASB + (lane >> 4) * 16;
        const uint32_t bBase = saB + st * STAGE +
            (wn * 32 + (lane & 7)) * ASB + (lane >> 3) * 16;
        uint32_t b[4][4];
#pragma unroll
        for (int nt = 0; nt < 4; nt++)
            LDSMX4(b[nt], bBase + nt * (8 * ASB));
#pragma unroll
        for (int sp = 0; sp < 2; sp++) {
            uint32_t a[4][4];
#pragma unroll
            for (int mt = 0; mt < 4; mt++)
                LDSMX4(a[mt], aBase + mt * (16 * ASB) + sp * 32);
#pragma unroll
            for (int mt = 0; mt < 4; mt++)
#pragma unroll
                for (int nt = 0; nt < 4; nt++)
                    mmaf16(acc[mt][nt], a[mt], b[nt][2 * sp], b[nt][2 * sp + 1]);
        }
    };

    const int NC = K / 32;
    issue(0); CPCOMMIT();
    issue(1); CPCOMMIT();
    for (int ch = 0; ch < NC - 1; ch++) {
        CPWAIT(1);
        __syncthreads();
        if (ch + 2 < NC) { issue(ch + 2); CPCOMMIT(); }
        compute(ch % 3);
    }
    CPWAIT(0);
    __syncthreads();
    compute((NC - 1) % 3);

    // epilogue
#pragma unroll
    for (int nt = 0; nt < 4; nt++) {
        const int col = n0 + wn * 32 + nt * 8 + (lane & 3) * 2;
        const float2 bv = *(const float2*)(bias + col);
#pragma unroll
        for (int mt = 0; mt < 4; mt++) {
            const int row = m0 + wm * 64 + mt * 16 + (lane >> 2);
            float2 v0, v1;
            v0.x = acc[mt][nt][0] + bv.x; v0.y = acc[mt][nt][1] + bv.y;
            v1.x = acc[mt][nt][2] + bv.x; v1.y = acc[mt][nt][3] + bv.y;
            if (RELU) {
                v0.x = fmaxf(v0.x, 0.f); v0.y = fmaxf(v0.y, 0.f);
                v1.x = fmaxf(v1.x, 0.f); v1.y = fmaxf(v1.y, 0.f);
            }
            if (MODE == 0) {
                float* Cf = (float*)C;
                *(float2*)(Cf + (size_t)row * ldc + col) = v0;
                *(float2*)(Cf + (size_t)(row + 8) * ldc + col) = v1;
            } else if (MODE == 2) {
                __half2* Ch = (__half2*)C;
                Ch[((size_t)row * ldc + col) >> 1]       = __floats2half2_rn(v0.x, v0.y);
                Ch[((size_t)(row + 8) * ldc + col) >> 1] = __floats2half2_rn(v1.x, v1.y);
            } else {
                if (n0 < 1024) {                       // Q: fp16 (pre-scaled)
                    __half2* qh = (__half2*)g_qh;
                    qh[((size_t)row * 1024 + col) >> 1]       = __floats2half2_rn(v0.x, v0.y);
                    qh[((size_t)(row + 8) * 1024 + col) >> 1] = __floats2half2_rn(v1.x, v1.y);
                } else if (n0 < 2048) {                // K: fp16 pairs [h][s][dk/2]
                    const int ck = col - 1024;
                    const int hh = ck >> 6, dk = ck & 63;
                    uint32_t* kb = g_kb + ((size_t)hh * S_LEN) * 32 + (dk >> 1);
                    kb[(size_t)row * 32]       = packh(v0.x, v0.y);
                    kb[(size_t)(row + 8) * 32] = packh(v1.x, v1.y);
                } else {                                // V: fp16 transposed [h][dk][s]
                    const int cv = col - 2048;
                    const int hh = cv >> 6, dk = cv & 63;
                    __half* vt = g_vt + ((size_t)(hh * 64 + dk)) * S_LEN;
                    vt[row]             = __float2half_rn(v0.x);
                    vt[S_LEN + row]     = __float2half_rn(v0.y);
                    vt[row + 8]         = __float2half_rn(v1.x);
                    vt[S_LEN + row + 8] = __float2half_rn(v1.y);
                }
            }
        }
    }
}

// ======================= fp16 flash attention (3-stage cp.async) ============
// grid (S/128, H), 256 threads, 8 warps each owning 16 Q rows.
// Q fp16 pre-scaled (direct 32-bit fragment loads). K fp16x2, V^T fp16,
// 3-stage cp.async. Softmax: pack f16x2 + ex2.approx.f16x2 == P A-fragment.
// Row sums via an extra mma with B == ones.
__global__ void __launch_bounds__(256, 2)
flash_f16()
{
    extern __shared__ uint32_t fsm[];
    uint32_t* Ks = fsm;                  // [3][64*36]
    uint32_t* Vs = fsm + 3 * 64 * 36;    // [3][64*36]
    const uint32_t ksA = smem_u32(Ks);
    const uint32_t vsA = smem_u32(Vs);
    constexpr uint32_t FST = 64 * 36 * 4;
    constexpr uint32_t ONES = 0x3C003C00u;   // fp16 (1.0, 1.0)

    const int tid = threadIdx.x, lane = tid & 31, wid = tid >> 5;
    const int h = blockIdx.y, qb = blockIdx.x * 128;
    const int row0 = wid * 16 + (lane >> 2);
    const int cq = lane & 3;

    const __half* Qg = g_qh + (size_t)qb * D_MODEL + h * DKH;
    const uint32_t* Kg = g_kb + ((size_t)h * S_LEN) * 32;
    const __half* Vg = g_vt + ((size_t)h * DKH) * S_LEN;

    uint32_t qa[4][4];
#pragma unroll
    for (int t = 0; t < 4; t++) {
        qa[t][0] = *(const uint32_t*)(Qg + (size_t)row0 * D_MODEL + 16 * t + 2 * cq);
        qa[t][1] = *(const uint32_t*)(Qg + (size_t)(row0 + 8) * D_MODEL + 16 * t + 2 * cq);
        qa[t][2] = *(const uint32_t*)(Qg + (size_t)row0 * D_MODEL + 16 * t + 8 + 2 * cq);
        qa[t][3] = *(const uint32_t*)(Qg + (size_t)(row0 + 8) * D_MODEL + 16 * t + 8 + 2 * cq);
    }

    auto issue = [&](int kt) {
        const int st = kt % 3;
        const uint32_t kd = ksA + st * FST;
        const uint32_t* kg = Kg + (size_t)(kt * 64) * 32;
#pragma unroll
        for (int j = 0; j < 2; j++) {
            const int idx = tid + j * 256;
            const int kv = idx >> 3, ch = idx & 7;
            CPASYNC(kd + (kv * 36 + ch * 4) * 4, kg + (size_t)kv * 32 + ch * 4);
        }
        const uint32_t vd = vsA + st * FST;
        const __half* vg = Vg + kt * 64;
#pragma unroll
        for (int j = 0; j < 2; j++) {
            const int idx = tid + j * 256;
            const int dk = idx >> 3, ch = idx & 7;
            CPASYNC(vd + (dk * 36 + ch * 4) * 4, vg + (size_t)dk * S_LEN + ch * 8);
        }
    };

    float oc[8][4];
#pragma unroll
    for (int dn = 0; dn < 8; dn++)
#pragma unroll
        for (int j = 0; j < 4; j++) oc[dn][j] = 0.f;
    float ocs[4] = {0.f, 0.f, 0.f, 0.f};

    constexpr int NT = S_LEN / 64;
    issue(0); CPCOMMIT();
    issue(1); CPCOMMIT();

    for (int kt = 0; kt < NT; kt++) {
        if (kt < NT - 1) { CPWAIT(1); } else { CPWAIT(0); }
        __syncthreads();
        if (kt + 2 < NT) { issue(kt + 2); CPCOMMIT(); }

        const int st = kt % 3;
        const uint32_t* Kp = Ks + st * (64 * 36);
        const uint32_t* Vp = Vs + st * (64 * 36);

        float sc[8][4];
#pragma unroll
        for (int nt = 0; nt < 8; nt++)
#pragma unroll
            for (int j = 0; j < 4; j++) sc[nt][j] = 0.f;
#pragma unroll
        for (int t = 0; t < 4; t++) {
#pragma unroll
            for (int nt = 0; nt < 8; nt++) {
                const uint32_t* p = &Kp[(nt * 8 + (lane >> 2)) * 36 + 8 * t + cq];
                mmaf16(sc[nt], qa[t], p[0], p[4]);
            }
        }

        uint32_t pa[4][4];
#pragma unroll
        for (int nt = 0; nt < 8; nt++) {
            const int u = nt >> 1, hi = (nt & 1) * 2;
            pa[u][hi]     = ex2h2(packh(sc[nt][0], sc[nt][1]));
            pa[u][hi + 1] = ex2h2(packh(sc[nt][2], sc[nt][3]));
        }

#pragma unroll
        for (int u = 0; u < 4; u++) {
            mmaf16(ocs, pa[u], ONES, ONES);
#pragma unroll
            for (int dn = 0; dn < 8; dn++) {
                const uint32_t* p = &Vp[(dn * 8 + (lane >> 2)) * 36 + 8 * u + cq];
                mmaf16(oc[dn], pa[u], p[0], p[4]);
            }
        }
        // next iteration's top-of-loop barrier orders the stage overwrite.
    }

    const float inv0 = 1.f / ocs[0];
    const float inv1 = 1.f / ocs[2];
    __half* o0 = g_cch + (size_t)(qb + row0) * D_MODEL + h * DKH;
    __half* o1 = g_cch + (size_t)(qb + row0 + 8) * D_MODEL + h * DKH;
#pragma unroll
    for (int dn = 0; dn < 8; dn++) {
        const int col = dn * 8 + 2 * cq;
        *(__half2*)(o0 + col) = __floats2half2_rn(oc[dn][0] * inv0, oc[dn][1] * inv0);
        *(__half2*)(o1 + col) = __floats2half2_rn(oc[dn][2] * inv1, oc[dn][3] * inv1);
    }
}

// ---------------- layernorm with residual: out = LN(a + b) -----------------
__global__ void ln_residual_kernel(const float* __restrict__ a,
                                   const float* __restrict__ b,
                                   const float* __restrict__ gw,
                                   const float* __restrict__ bw,
                                   float* __restrict__ out,
                                   __half* __restrict__ out_h)
{
    const int row = blockIdx.x;
    const int t = threadIdx.x;
    const float* ar = a + (size_t)row * D_MODEL;
    const float* br = b + (size_t)row * D_MODEL;

    float v[4];
    float s1 = 0.f, s2 = 0.f;
#pragma unroll
    for (int i = 0; i < 4; i++) {
        const int c = t + i * 256;
        const float x = ar[c] + br[c];
        v[i] = x;
        s1 += x;
        s2 += x * x;
    }
#pragma unroll
    for (int o = 16; o; o >>= 1) {
        s1 += __shfl_xor_sync(0xffffffffu, s1, o);
        s2 += __shfl_xor_sync(0xffffffffu, s2, o);
    }
    __shared__ float r1[8], r2[8];
    __shared__ float mu_s, rs_s;
    if ((t & 31) == 0) { r1[t >> 5] = s1; r2[t >> 5] = s2; }
    __syncthreads();
    if (t == 0) {
        float a1 = 0.f, a2 = 0.f;
#pragma unroll
        for (int i = 0; i < 8; i++) { a1 += r1[i]; a2 += r2[i]; }
        const float mu = a1 * (1.f / D_MODEL);
        const float var = a2 * (1.f / D_MODEL) - mu * mu;
        mu_s = mu;
        rs_s = rsqrtf(var + 1e-5f);
    }
    __syncthreads();
    const float mu = mu_s, rs = rs_s;
    float* orow = out + (size_t)row * D_MODEL;
    __half* hrow = out_h ? out_h + (size_t)row * D_MODEL : nullptr;
#pragma unroll
    for (int i = 0; i < 4; i++) {
        const int c = t + i * 256;
        const float y = (v[i] - mu) * rs * gw[c] + bw[c];
        orow[c] = y;
        if (out_h) hrow[c] = __float2half_rn(y);
    }
}

// ---------------- launch ----------------------------------------------------
extern "C" void kernel_launch(void* const* d_in, const int* in_sizes, int n_in,
                              void* d_out, int out_size)
{
    (void)in_sizes; (void)n_in; (void)out_size;
    const float* src   = (const float*)d_in[0];
    const float* Wq    = (const float*)d_in[1];
    const float* bq    = (const float*)d_in[2];
    const float* Wk    = (const float*)d_in[3];
    const float* bk    = (const float*)d_in[4];
    const float* Wv    = (const float*)d_in[5];
    const float* bv    = (const float*)d_in[6];
    const float* Wo    = (const float*)d_in[7];
    const float* bo    = (const float*)d_in[8];
    const float* ln1_g = (const float*)d_in[9];
    const float* ln1_b = (const float*)d_in[10];
    const float* W1    = (const float*)d_in[11];
    const float* b1    = (const float*)d_in[12];
    const float* W2    = (const float*)d_in[13];
    const float* b2    = (const float*)d_in[14];
    const float* ln2_g = (const float*)d_in[15];
    const float* ln2_b = (const float*)d_in[16];
    float* out = (float*)d_out;

    void *psrch, *pwo, *pw1, *pw2, *pcch, *ptmp, *px1, *px1h, *ph1h, *pwqkv, *pbqkv;
    cudaGetSymbolAddress(&psrch, g_srch);
    cudaGetSymbolAddress(&pwqkv, g_wqkv);
    cudaGetSymbolAddress(&pbqkv, g_bqkv);
    cudaGetSymbolAddress(&pwo, g_wo);
    cudaGetSymbolAddress(&pw1, g_w1);
    cudaGetSymbolAddress(&pw2, g_w2);
    cudaGetSymbolAddress(&pcch, g_cch);
    cudaGetSymbolAddress(&ptmp, g_tmp);
    cudaGetSymbolAddress(&px1, g_x1);
    cudaGetSymbolAddress(&px1h, g_x1h);
    cudaGetSymbolAddress(&ph1h, g_h1h);

    const int GSMEM = 6 * 128 * 80;              // 61440 B -> 2 CTAs/SM
    const int FSMEM = 6 * 64 * 36 * 4;           // 55296 B -> 2 CTAs/SM
    cudaFuncSetAttribute(gemm_f16<0, false>,
                         cudaFuncAttributeMaxDynamicSharedMemorySize, GSMEM);
    cudaFuncSetAttribute(gemm_f16<2, true>,
                         cudaFuncAttributeMaxDynamicSharedMemorySize, GSMEM);
    cudaFuncSetAttribute(gemm_f16<1, false>,
                         cudaFuncAttributeMaxDynamicSharedMemorySize, GSMEM);
    cudaFuncSetAttribute(flash_f16,
                         cudaFuncAttributeMaxDynamicSharedMemorySize, FSMEM);

    // ---- prep: 3 launches ----
    half_copy_bias<<<(S_LEN * D_MODEL / 4 + 255) / 256, 256>>>(
        (const float4*)src, (__half2*)psrch, S_LEN * D_MODEL / 4, bq, bk, bv);
    transpose_all<<<1024 + 4096 + 4096, dim3(32, 8)>>>(Wo, W1, W2);
    pack_qkvT3<<<dim3(2, 32, 48), dim3(32, 8)>>>(Wq, Wk, Wv);

    // ---- fused QKV: [4096,1024] x [1024,3072]; writes g_qh/g_kb/g_vt ----
    gemm_f16<1, false><<<dim3(3072 / 128, S_LEN / 128), 256, GSMEM>>>(
        (const __half*)psrch, (const __half*)pwqkv, (const float*)pbqkv,
        nullptr, D_MODEL, D_MODEL, D_MODEL, 0);

    // ---- attention -> g_cch [S, H*DK] fp16 ----
    flash_f16<<<dim3(S_LEN / 128, NH), 256, FSMEM>>>();

    // ---- output projection [4096,1024] x [1024,1024] -> fp32 tmp ----
    gemm_f16<0, false><<<dim3(D_MODEL / 128, S_LEN / 128), 256, GSMEM>>>(
        (const __half*)pcch, (const __half*)pwo, bo, ptmp,
        D_MODEL, D_MODEL, D_MODEL, D_MODEL);
    // x1 = LN(src + attn_out): fp32 + fp16 copy
    ln_residual_kernel<<<S_LEN, 256>>>(src, (const float*)ptmp, ln1_g, ln1_b,
                                       (float*)px1, (__half*)px1h);

    // ---- FFN up: relu(x1 @ W1 + b1) -> fp16 h1 ----
    gemm_f16<2, true><<<dim3(FF / 128, S_LEN / 128), 256, GSMEM>>>(
        (const __half*)px1h, (const __half*)pw1, b1, ph1h,
        D_MODEL, D_MODEL, D_MODEL, FF);
    // ---- FFN down: h1 @ W2 + b2 -> fp32 tmp ----
    gemm_f16<0, false><<<dim3(D_MODEL / 128, S_LEN / 128), 256, GSMEM>>>(
        (const __half*)ph1h, (const __half*)pw2, b2, ptmp,
        FF, FF, FF, D_MODEL);
    // out = LN(x1 + ffn), exact fp32
    ln_residual_kernel<<<S_LEN, 256>>>((const float*)px1, (const float*)ptmp,
                                       ln2_g, ln2_b, out, nullptr);
}

// round 16
// speedup vs baseline: 1.3520x; 1.3520x over previous
#include <cuda_runtime.h>
#include <cuda_fp16.h>
#include <cstdint>
#include <cstddef>
#include <math.h>

#define S_LEN   4096
#define D_MODEL 1024
#define NH      16
#define DKH     64
#define FF      4096

// ---------------- scratch (device globals: no allocation allowed) ----------
__device__ __half g_srch[S_LEN * D_MODEL];       // fp16 src
__device__ __half g_wqkv[3072 * D_MODEL];        // transposed [3072,1024] fp16 (Wq pre-scaled)
__device__ float  g_bqkv[3072];                  // bq pre-scaled
__device__ __half g_wo[D_MODEL * D_MODEL];       // transposed [N,K] fp16
__device__ __half g_w1[FF * D_MODEL];
__device__ __half g_w2[D_MODEL * FF];
__device__ __half g_qh[S_LEN * D_MODEL];         // Q fp16 [S,1024] (pre-scaled)
__device__ uint32_t g_kb[NH * S_LEN * 32];       // K fp16x2 [h][s][dk/2]
__device__ __half g_vt[NH * DKH * S_LEN];        // V^T fp16 [h][dk][s]
__device__ __half g_cch[S_LEN * D_MODEL];        // concat fp16
__device__ float  g_tmp[S_LEN * D_MODEL];
__device__ float  g_x1[S_LEN * D_MODEL];         // x1 fp32 (residual for LN2)
__device__ __half g_x1h[S_LEN * D_MODEL];        // x1 fp16 (FFN1 A)
__device__ __half g_h1h[S_LEN * FF];             // relu(ffn1) fp16 (FFN2 A)

#define QK_SCALE 0.18033688011112042591999058f    // 0.125 * log2(e)

// ---------------- helpers ---------------------------------------------------
__device__ __forceinline__ uint32_t packh(float lo, float hi) {
    uint32_t r;
    asm("cvt.rn.f16x2.f32 %0, %1, %2;" : "=r"(r) : "f"(hi), "f"(lo));
    return r;
}

__device__ __forceinline__ uint32_t ex2h2(uint32_t x) {
    uint32_t y;
    asm("ex2.approx.f16x2 %0, %1;" : "=r"(y) : "r"(x));
    return y;
}

__device__ __forceinline__ uint32_t smem_u32(const void* p) {
    uint32_t a;
    asm("{ .reg .u64 t; cvta.to.shared.u64 t, %1; cvt.u32.u64 %0, t; }"
        : "=r"(a) : "l"(p));
    return a;
}

// m16n8k16 fp16 HMMA, fp32 accum, D += A*B
__device__ __forceinline__ void mmaf16(float c[4], const uint32_t a[4],
                                       uint32_t b0, uint32_t b1) {
    asm volatile(
        "mma.sync.aligned.m16n8k16.row.col.f32.f16.f16.f32 "
        "{%0,%1,%2,%3}, {%4,%5,%6,%7}, {%8,%9}, {%0,%1,%2,%3};"
        : "+f"(c[0]), "+f"(c[1]), "+f"(c[2]), "+f"(c[3])
        : "r"(a[0]), "r"(a[1]), "r"(a[2]), "r"(a[3]), "r"(b0), "r"(b1));
}

#define LDSMX4(r, a) \
    asm volatile("ldmatrix.sync.aligned.m8n8.x4.shared.b16 {%0,%1,%2,%3}, [%4];" \
        : "=r"((r)[0]), "=r"((r)[1]), "=r"((r)[2]), "=r"((r)[3]) : "r"(a))

#define CPASYNC(dst, src) \
    asm volatile("cp.async.cg.shared.global [%0], [%1], 16;" :: "r"(dst), "l"(src))
#define CPCOMMIT() asm volatile("cp.async.commit_group;" ::: "memory")
#define CPWAIT(n)  asm volatile("cp.async.wait_group %0;" :: "n"(n) : "memory")

// ---------------- prep kernels (3 launches) ----------------------------------
__global__ void half_copy_bias(const float4* __restrict__ x, __half2* __restrict__ y,
                               int n4, const float* __restrict__ bq,
                               const float* __restrict__ bk,
                               const float* __restrict__ bv) {
    const int i = blockIdx.x * 256 + threadIdx.x;
    if (i < n4) {
        float4 v = x[i];
        y[2 * i]     = __floats2half2_rn(v.x, v.y);
        y[2 * i + 1] = __floats2half2_rn(v.z, v.w);
    }
    if (i < D_MODEL) {
        g_bqkv[i] = bq[i] * QK_SCALE;      // Q bias pre-scaled
        g_bqkv[i + 1024] = bk[i];
        g_bqkv[i + 2048] = bv[i];
    }
}

// fused transpose of Wo/W1/W2 (f32 [R][C] -> fp16 [C][R]), 1-D decoded grid
__global__ void transpose_all(const float* __restrict__ Wo,
                              const float* __restrict__ W1,
                              const float* __restrict__ W2) {
    __shared__ float t[32][33];
    int id = blockIdx.x;
    const float* src;
    __half* dst;
    int R, C, bx, by;
    if (id < 1024) {                       // Wo: 1024x1024
        src = Wo; dst = g_wo; R = D_MODEL; C = D_MODEL;
        bx = (id & 31) * 32; by = (id >> 5) * 32;
    } else if (id < 1024 + 4096) {         // W1: [1024,4096] -> [4096,1024]
        id -= 1024;
        src = W1; dst = g_w1; R = D_MODEL; C = FF;
        bx = (id & 127) * 32; by = (id >> 7) * 32;
    } else {                               // W2: [4096,1024] -> [1024,4096]
        id -= 1024 + 4096;
        src = W2; dst = g_w2; R = FF; C = D_MODEL;
        bx = (id & 31) * 32; by = (id >> 5) * 32;
    }
    const int tx = threadIdx.x, ty = threadIdx.y;
    {
        const int x = bx + tx;
#pragma unroll
        for (int j = 0; j < 32; j += 8)
            t[ty + j][tx] = src[(size_t)(by + ty + j) * C + x];
    }
    __syncthreads();
    {
        const int x = by + tx;
#pragma unroll
        for (int j = 0; j < 32; j += 8)
            dst[(size_t)(bx + ty + j) * R + x] = __float2half_rn(t[tx][ty + j]);
    }
}

// QKV weights [NH][1024][64] -> g_wqkv [3*NH*64][1024] fp16; Wq pre-scaled
__global__ void pack_qkvT3(const float* __restrict__ Wq, const float* __restrict__ Wk,
                           const float* __restrict__ Wv) {
    __shared__ float t[32][33];
    const int which = blockIdx.z >> 4;          // 0=q,1=k,2=v
    const int head = blockIdx.z & 15;
    const float* W = (which == 0) ? Wq : (which == 1) ? Wk : Wv;
    const float sc = (which == 0) ? (float)QK_SCALE : 1.0f;
    const float* s = W + (size_t)head * D_MODEL * DKH;
    __half* d = g_wqkv + ((size_t)which * 1024 + head * DKH) * D_MODEL;
    const int tx = threadIdx.x, ty = threadIdx.y;
    {
        const int x = blockIdx.x * 32 + tx;          // dk
#pragma unroll
        for (int j = 0; j < 32; j += 8)
            t[ty + j][tx] = s[(size_t)(blockIdx.y * 32 + ty + j) * DKH + x];
    }
    __syncthreads();
    {
        const int x = blockIdx.y * 32 + tx;          // d
#pragma unroll
        for (int j = 0; j < 32; j += 8)
            d[(size_t)(blockIdx.x * 32 + ty + j) * D_MODEL + x] =
                __float2half_rn(t[tx][ty + j] * sc);
    }
}

// ======================= FP16 GEMM (ldmatrix + cp.async 3-stage) =============
// C = A @ Bt^T + bias. A [M,K] half (lda), Bt [N,K] half (ldb).
// CTA 128x128, 128 threads, 4 warps 2x2, warp tile 64x64, k-chunk 32.
// 3-stage / 61440 B smem -> 2 CTAs/SM (validated local optimum; R7/R13/R15
// showed every perturbation of this envelope regresses).
// MODE 0: fp32 C.  MODE 1: QKV (Q fp16 pre-scaled / K fp16x2 / V^T fp16).
// MODE 2: half C (+ ReLU via RELU flag).
template <int MODE, bool RELU>
__global__ void __launch_bounds__(128)
gemm_f16(const __half* __restrict__ A, const __half* __restrict__ Bt,
         const float* __restrict__ bias, void* __restrict__ C,
         int K, int lda, int ldb, int ldc)
{
    constexpr int ASB = 80;                      // bytes per smem row
    constexpr uint32_t STAGE = 128 * ASB;        // 10240 B
    extern __shared__ uint32_t dsm[];
    const uint32_t saA = smem_u32(dsm);
    const uint32_t saB = saA + 3 * STAGE;

    const int tid = threadIdx.x, lane = tid & 31, wid = tid >> 5;
    const int wm = wid >> 1, wn = wid & 1;
    const int m0 = blockIdx.y * 128, n0 = blockIdx.x * 128;

    const __half* Ab = A + (size_t)m0 * lda;
    const __half* Bb = Bt + (size_t)n0 * ldb;

    float acc[4][8][4];
#pragma unroll
    for (int mt = 0; mt < 4; mt++)
#pragma unroll
        for (int nt = 0; nt < 8; nt++)
#pragma unroll
            for (int j = 0; j < 4; j++) acc[mt][nt][j] = 0.f;

    auto issue = [&](int ch) {
        const int st = ch % 3;
        const __half* Ac = Ab + ch * 32;
        const uint32_t ad = saA + st * STAGE;
#pragma unroll
        for (int i = 0; i < 4; i++) {
            const int idx = tid + i * 128;
            const int r = idx >> 2, q = idx & 3;
            CPASYNC(ad + r * ASB + q * 16, Ac + (size_t)r * lda + q * 8);
        }
        const __half* Bc = Bb + ch * 32;
        const uint32_t bd = saB + st * STAGE;
#pragma unroll
        for (int i = 0; i < 4; i++) {
            const int idx = tid + i * 128;
            const int r = idx >> 2, q = idx & 3;
            CPASYNC(bd + r * ASB + q * 16, Bc + (size_t)r * ldb + q * 8);
        }
    };

    auto compute = [&](int st) {
        const uint32_t aBase = saA + st * STAGE +
            (wm * 64 + (lane & 15)) * ASB + (lane >> 4) * 16;
        const uint32_t bBase = saB + st * STAGE +
            (wn * 64 + (lane & 7)) * ASB + (lane >> 3) * 16;
        uint32_t b[8][4];
#pragma unroll
        for (int nt = 0; nt < 8; nt++)
            LDSMX4(b[nt], bBase + nt * (8 * ASB));
#pragma unroll
        for (int sp = 0; sp < 2; sp++) {
            uint32_t a[4][4];
#pragma unroll
            for (int mt = 0; mt < 4; mt++)
                LDSMX4(a[mt], aBase + mt * (16 * ASB) + sp * 32);
#pragma unroll
            for (int mt = 0; mt < 4; mt++)
#pragma unroll
                for (int nt = 0; nt < 8; nt++)
                    mmaf16(acc[mt][nt], a[mt], b[nt][2 * sp], b[nt][2 * sp + 1]);
        }
    };

    const int NC = K / 32;
    issue(0); CPCOMMIT();
    issue(1); CPCOMMIT();
    for (int ch = 0; ch < NC - 1; ch++) {
        CPWAIT(1);
        __syncthreads();
        if (ch + 2 < NC) { issue(ch + 2); CPCOMMIT(); }
        compute(ch % 3);
    }
    CPWAIT(0);
    __syncthreads();
    compute((NC - 1) % 3);

    // epilogue
#pragma unroll
    for (int nt = 0; nt < 8; nt++) {
        const int col = n0 + wn * 64 + nt * 8 + (lane & 3) * 2;
        const float2 bv = *(const float2*)(bias + col);
#pragma unroll
        for (int mt = 0; mt < 4; mt++) {
            const int row = m0 + wm * 64 + mt * 16 + (lane >> 2);
            float2 v0, v1;
            v0.x = acc[mt][nt][0] + bv.x; v0.y = acc[mt][nt][1] + bv.y;
            v1.x = acc[mt][nt][2] + bv.x; v1.y = acc[mt][nt][3] + bv.y;
            if (RELU) {
                v0.x = fmaxf(v0.x, 0.f); v0.y = fmaxf(v0.y, 0.f);
                v1.x = fmaxf(v1.x, 0.f); v1.y = fmaxf(v1.y, 0.f);
            }
            if (MODE == 0) {
                float* Cf = (float*)C;
                *(float2*)(Cf + (size_t)row * ldc + col) = v0;
                *(float2*)(Cf + (size_t)(row + 8) * ldc + col) = v1;
            } else if (MODE == 2) {
                __half2* Ch = (__half2*)C;
                Ch[((size_t)row * ldc + col) >> 1]       = __floats2half2_rn(v0.x, v0.y);
                Ch[((size_t)(row + 8) * ldc + col) >> 1] = __floats2half2_rn(v1.x, v1.y);
            } else {
                if (n0 < 1024) {                       // Q: fp16 (pre-scaled)
                    __half2* qh = (__half2*)g_qh;
                    qh[((size_t)row * 1024 + col) >> 1]       = __floats2half2_rn(v0.x, v0.y);
                    qh[((size_t)(row + 8) * 1024 + col) >> 1] = __floats2half2_rn(v1.x, v1.y);
                } else if (n0 < 2048) {                // K: fp16 pairs [h][s][dk/2]
                    const int ck = col - 1024;
                    const int hh = ck >> 6, dk = ck & 63;
                    uint32_t* kb = g_kb + ((size_t)hh * S_LEN) * 32 + (dk >> 1);
                    kb[(size_t)row * 32]       = packh(v0.x, v0.y);
                    kb[(size_t)(row + 8) * 32] = packh(v1.x, v1.y);
                } else {                                // V: fp16 transposed [h][dk][s]
                    const int cv = col - 2048;
                    const int hh = cv >> 6, dk = cv & 63;
                    __half* vt = g_vt + ((size_t)(hh * 64 + dk)) * S_LEN;
                    vt[row]             = __float2half_rn(v0.x);
                    vt[S_LEN + row]     = __float2half_rn(v0.y);
                    vt[row + 8]         = __float2half_rn(v1.x);
                    vt[S_LEN + row + 8] = __float2half_rn(v1.y);
                }
            }
        }
    }
}

// ======================= fp16 flash attention (3-stage cp.async) ============
// grid (S/128, H), 256 threads, 8 warps each owning 16 Q rows.
// Q fp16 pre-scaled (direct 32-bit fragment loads). K fp16x2, V^T fp16,
// 3-stage cp.async. Softmax: pack f16x2 + ex2.approx.f16x2 == P A-fragment.
// Row sums via an extra mma with B == ones.
__global__ void __launch_bounds__(256, 2)
flash_f16()
{
    extern __shared__ uint32_t fsm[];
    uint32_t* Ks = fsm;                  // [3][64*36]
    uint32_t* Vs = fsm + 3 * 64 * 36;    // [3][64*36]
    const uint32_t ksA = smem_u32(Ks);
    const uint32_t vsA = smem_u32(Vs);
    constexpr uint32_t FST = 64 * 36 * 4;
    constexpr uint32_t ONES = 0x3C003C00u;   // fp16 (1.0, 1.0)

    const int tid = threadIdx.x, lane = tid & 31, wid = tid >> 5;
    const int h = blockIdx.y, qb = blockIdx.x * 128;
    const int row0 = wid * 16 + (lane >> 2);
    const int cq = lane & 3;

    const __half* Qg = g_qh + (size_t)qb * D_MODEL + h * DKH;
    const uint32_t* Kg = g_kb + ((size_t)h * S_LEN) * 32;
    const __half* Vg = g_vt + ((size_t)h * DKH) * S_LEN;

    uint32_t qa[4][4];
#pragma unroll
    for (int t = 0; t < 4; t++) {
        qa[t][0] = *(const uint32_t*)(Qg + (size_t)row0 * D_MODEL + 16 * t + 2 * cq);
        qa[t][1] = *(const uint32_t*)(Qg + (size_t)(row0 + 8) * D_MODEL + 16 * t + 2 * cq);
        qa[t][2] = *(const uint32_t*)(Qg + (size_t)row0 * D_MODEL + 16 * t + 8 + 2 * cq);
        qa[t][3] = *(const uint32_t*)(Qg + (size_t)(row0 + 8) * D_MODEL + 16 * t + 8 + 2 * cq);
    }

    auto issue = [&](int kt) {
        const int st = kt % 3;
        const uint32_t kd = ksA + st * FST;
        const uint32_t* kg = Kg + (size_t)(kt * 64) * 32;
#pragma unroll
        for (int j = 0; j < 2; j++) {
            const int idx = tid + j * 256;
            const int kv = idx >> 3, ch = idx & 7;
            CPASYNC(kd + (kv * 36 + ch * 4) * 4, kg + (size_t)kv * 32 + ch * 4);
        }
        const uint32_t vd = vsA + st * FST;
        const __half* vg = Vg + kt * 64;
#pragma unroll
        for (int j = 0; j < 2; j++) {
            const int idx = tid + j * 256;
            const int dk = idx >> 3, ch = idx & 7;
            CPASYNC(vd + (dk * 36 + ch * 4) * 4, vg + (size_t)dk * S_LEN + ch * 8);
        }
    };

    float oc[8][4];
#pragma unroll
    for (int dn = 0; dn < 8; dn++)
#pragma unroll
        for (int j = 0; j < 4; j++) oc[dn][j] = 0.f;
    float ocs[4] = {0.f, 0.f, 0.f, 0.f};

    constexpr int NT = S_LEN / 64;
    issue(0); CPCOMMIT();
    issue(1); CPCOMMIT();

    for (int kt = 0; kt < NT; kt++) {
        if (kt < NT - 1) { CPWAIT(1); } else { CPWAIT(0); }
        __syncthreads();
        if (kt + 2 < NT) { issue(kt + 2); CPCOMMIT(); }

        const int st = kt % 3;
        const uint32_t* Kp = Ks + st * (64 * 36);
        const uint32_t* Vp = Vs + st * (64 * 36);

        float sc[8][4];
#pragma unroll
        for (int nt = 0; nt < 8; nt++)
#pragma unroll
            for (int j = 0; j < 4; j++) sc[nt][j] = 0.f;
#pragma unroll
        for (int t = 0; t < 4; t++) {
#pragma unroll
            for (int nt = 0; nt < 8; nt++) {
                const uint32_t* p = &Kp[(nt * 8 + (lane >> 2)) * 36 + 8 * t + cq];
                mmaf16(sc[nt], qa[t], p[0], p[4]);
            }
        }

        uint32_t pa[4][4];
#pragma unroll
        for (int nt = 0; nt < 8; nt++) {
            const int u = nt >> 1, hi = (nt & 1) * 2;
            pa[u][hi]     = ex2h2(packh(sc[nt][0], sc[nt][1]));
            pa[u][hi + 1] = ex2h2(packh(sc[nt][2], sc[nt][3]));
        }

#pragma unroll
        for (int u = 0; u < 4; u++) {
            mmaf16(ocs, pa[u], ONES, ONES);
#pragma unroll
            for (int dn = 0; dn < 8; dn++) {
                const uint32_t* p = &Vp[(dn * 8 + (lane >> 2)) * 36 + 8 * u + cq];
                mmaf16(oc[dn], pa[u], p[0], p[4]);
            }
        }
        // next iteration's top-of-loop barrier orders the stage overwrite.
    }

    const float inv0 = 1.f / ocs[0];
    const float inv1 = 1.f / ocs[2];
    __half* o0 = g_cch + (size_t)(qb + row0) * D_MODEL + h * DKH;
    __half* o1 = g_cch + (size_t)(qb + row0 + 8) * D_MODEL + h * DKH;
#pragma unroll
    for (int dn = 0; dn < 8; dn++) {
        const int col = dn * 8 + 2 * cq;
        *(__half2*)(o0 + col) = __floats2half2_rn(oc[dn][0] * inv0, oc[dn][1] * inv0);
        *(__half2*)(o1 + col) = __floats2half2_rn(oc[dn][2] * inv1, oc[dn][3] * inv1);
    }
}

// ---------------- layernorm with residual: out = LN(a + b) -----------------
__global__ void ln_residual_kernel(const float* __restrict__ a,
                                   const float* __restrict__ b,
                                   const float* __restrict__ gw,
                                   const float* __restrict__ bw,
                                   float* __restrict__ out,
                                   __half* __restrict__ out_h)
{
    const int row = blockIdx.x;
    const int t = threadIdx.x;
    const float* ar = a + (size_t)row * D_MODEL;
    const float* br = b + (size_t)row * D_MODEL;

    float v[4];
    float s1 = 0.f, s2 = 0.f;
#pragma unroll
    for (int i = 0; i < 4; i++) {
        const int c = t + i * 256;
        const float x = ar[c] + br[c];
        v[i] = x;
        s1 += x;
        s2 += x * x;
    }
#pragma unroll
    for (int o = 16; o; o >>= 1) {
        s1 += __shfl_xor_sync(0xffffffffu, s1, o);
        s2 += __shfl_xor_sync(0xffffffffu, s2, o);
    }
    __shared__ float r1[8], r2[8];
    __shared__ float mu_s, rs_s;
    if ((t & 31) == 0) { r1[t >> 5] = s1; r2[t >> 5] = s2; }
    __syncthreads();
    if (t == 0) {
        float a1 = 0.f, a2 = 0.f;
#pragma unroll
        for (int i = 0; i < 8; i++) { a1 += r1[i]; a2 += r2[i]; }
        const float mu = a1 * (1.f / D_MODEL);
        const float var = a2 * (1.f / D_MODEL) - mu * mu;
        mu_s = mu;
        rs_s = rsqrtf(var + 1e-5f);
    }
    __syncthreads();
    const float mu = mu_s, rs = rs_s;
    float* orow = out + (size_t)row * D_MODEL;
    __half* hrow = out_h ? out_h + (size_t)row * D_MODEL : nullptr;
#pragma unroll
    for (int i = 0; i < 4; i++) {
        const int c = t + i * 256;
        const float y = (v[i] - mu) * rs * gw[c] + bw[c];
        orow[c] = y;
        if (out_h) hrow[c] = __float2half_rn(y);
    }
}

// ---------------- launch ----------------------------------------------------
extern "C" void kernel_launch(void* const* d_in, const int* in_sizes, int n_in,
                              void* d_out, int out_size)
{
    (void)in_sizes; (void)n_in; (void)out_size;
    const float* src   = (const float*)d_in[0];
    const float* Wq    = (const float*)d_in[1];
    const float* bq    = (const float*)d_in[2];
    const float* Wk    = (const float*)d_in[3];
    const float* bk    = (const float*)d_in[4];
    const float* Wv    = (const float*)d_in[5];
    const float* bv    = (const float*)d_in[6];
    const float* Wo    = (const float*)d_in[7];
    const float* bo    = (const float*)d_in[8];
    const float* ln1_g = (const float*)d_in[9];
    const float* ln1_b = (const float*)d_in[10];
    const float* W1    = (const float*)d_in[11];
    const float* b1    = (const float*)d_in[12];
    const float* W2    = (const float*)d_in[13];
    const float* b2    = (const float*)d_in[14];
    const float* ln2_g = (const float*)d_in[15];
    const float* ln2_b = (const float*)d_in[16];
    float* out = (float*)d_out;

    void *psrch, *pwo, *pw1, *pw2, *pcch, *ptmp, *px1, *px1h, *ph1h, *pwqkv, *pbqkv;
    cudaGetSymbolAddress(&psrch, g_srch);
    cudaGetSymbolAddress(&pwqkv, g_wqkv);
    cudaGetSymbolAddress(&pbqkv, g_bqkv);
    cudaGetSymbolAddress(&pwo, g_wo);
    cudaGetSymbolAddress(&pw1, g_w1);
    cudaGetSymbolAddress(&pw2, g_w2);
    cudaGetSymbolAddress(&pcch, g_cch);
    cudaGetSymbolAddress(&ptmp, g_tmp);
    cudaGetSymbolAddress(&px1, g_x1);
    cudaGetSymbolAddress(&px1h, g_x1h);
    cudaGetSymbolAddress(&ph1h, g_h1h);

    const int GSMEM = 6 * 128 * 80;              // 61440 B -> 2 CTAs/SM
    const int FSMEM = 6 * 64 * 36 * 4;           // 55296 B -> 2 CTAs/SM
    cudaFuncSetAttribute(gemm_f16<0, false>,
                         cudaFuncAttributeMaxDynamicSharedMemorySize, GSMEM);
    cudaFuncSetAttribute(gemm_f16<2, true>,
                         cudaFuncAttributeMaxDynamicSharedMemorySize, GSMEM);
    cudaFuncSetAttribute(gemm_f16<1, false>,
                         cudaFuncAttributeMaxDynamicSharedMemorySize, GSMEM);
    cudaFuncSetAttribute(flash_f16,
                         cudaFuncAttributeMaxDynamicSharedMemorySize, FSMEM);

    // ---- prep: 3 launches ----
    half_copy_bias<<<(S_LEN * D_MODEL / 4 + 255) / 256, 256>>>(
        (const float4*)src, (__half2*)psrch, S_LEN * D_MODEL / 4, bq, bk, bv);
    transpose_all<<<1024 + 4096 + 4096, dim3(32, 8)>>>(Wo, W1, W2);
    pack_qkvT3<<<dim3(2, 32, 48), dim3(32, 8)>>>(Wq, Wk, Wv);

    // ---- fused QKV: [4096,1024] x [1024,3072]; writes g_qh/g_kb/g_vt ----
    gemm_f16<1, false><<<dim3(3072 / 128, S_LEN / 128), 128, GSMEM>>>(
        (const __half*)psrch, (const __half*)pwqkv, (const float*)pbqkv,
        nullptr, D_MODEL, D_MODEL, D_MODEL, 0);

    // ---- attention -> g_cch [S, H*DK] fp16 ----
    flash_f16<<<dim3(S_LEN / 128, NH), 256, FSMEM>>>();

    // ---- output projection [4096,1024] x [1024,1024] -> fp32 tmp ----
    gemm_f16<0, false><<<dim3(D_MODEL / 128, S_LEN / 128), 128, GSMEM>>>(
        (const __half*)pcch, (const __half*)pwo, bo, ptmp,
        D_MODEL, D_MODEL, D_MODEL, D_MODEL);
    // x1 = LN(src + attn_out): fp32 + fp16 copy
    ln_residual_kernel<<<S_LEN, 256>>>(src, (const float*)ptmp, ln1_g, ln1_b,
                                       (float*)px1, (__half*)px1h);

    // ---- FFN up: relu(x1 @ W1 + b1) -> fp16 h1 ----
    gemm_f16<2, true><<<dim3(FF / 128, S_LEN / 128), 128, GSMEM>>>(
        (const __half*)px1h, (const __half*)pw1, b1, ph1h,
        D_MODEL, D_MODEL, D_MODEL, FF);
    // ---- FFN down: h1 @ W2 + b2 -> fp32 tmp ----
    gemm_f16<0, false><<<dim3(D_MODEL / 128, S_LEN / 128), 128, GSMEM>>>(
        (const __half*)ph1h, (const __half*)pw2, b2, ptmp,
        FF, FF, FF, D_MODEL);
    // out = LN(x1 + ffn), exact fp32
    ln_residual_kernel<<<S_LEN, 256>>>((const float*)px1, (const float*)ptmp,
                                       ln2_g, ln2_b, out, nullptr);
}

// round 17
// speedup vs baseline: 1.3576x; 1.0041x over previous
#include <cuda_runtime.h>
#include <cuda_fp16.h>
#include <cstdint>
#include <cstddef>
#include <math.h>

#define S_LEN   4096
#define D_MODEL 1024
#define NH      16
#define DKH     64
#define FF      4096

// ---------------- scratch (device globals: no allocation allowed) ----------
__device__ __half g_srch[S_LEN * D_MODEL];       // fp16 src
__device__ __half g_wqkv[3072 * D_MODEL];        // transposed [3072,1024] fp16 (Wq pre-scaled)
__device__ float  g_bqkv[3072];                  // bq pre-scaled
__device__ __half g_wo[D_MODEL * D_MODEL];       // transposed [N,K] fp16
__device__ __half g_w1[FF * D_MODEL];
__device__ __half g_w2[D_MODEL * FF];
__device__ __half g_qh[S_LEN * D_MODEL];         // Q fp16 [S,1024] (pre-scaled)
__device__ uint32_t g_kb[NH * S_LEN * 32];       // K fp16x2 [h][s][dk/2]
__device__ __half g_vt[NH * DKH * S_LEN];        // V^T fp16 [h][dk][s]
__device__ __half g_cch[S_LEN * D_MODEL];        // concat fp16
__device__ __half g_tmph[S_LEN * D_MODEL];       // attn_out / ffn_out fp16
__device__ float  g_x1[S_LEN * D_MODEL];         // x1 fp32 (residual for LN2)
__device__ __half g_x1h[S_LEN * D_MODEL];        // x1 fp16 (FFN1 A)
__device__ __half g_h1h[S_LEN * FF];             // relu(ffn1) fp16 (FFN2 A)

#define QK_SCALE 0.18033688011112042591999058f    // 0.125 * log2(e)

// ---------------- helpers ---------------------------------------------------
__device__ __forceinline__ uint32_t packh(float lo, float hi) {
    uint32_t r;
    asm("cvt.rn.f16x2.f32 %0, %1, %2;" : "=r"(r) : "f"(hi), "f"(lo));
    return r;
}

__device__ __forceinline__ uint32_t ex2h2(uint32_t x) {
    uint32_t y;
    asm("ex2.approx.f16x2 %0, %1;" : "=r"(y) : "r"(x));
    return y;
}

__device__ __forceinline__ uint32_t smem_u32(const void* p) {
    uint32_t a;
    asm("{ .reg .u64 t; cvta.to.shared.u64 t, %1; cvt.u32.u64 %0, t; }"
        : "=r"(a) : "l"(p));
    return a;
}

// m16n8k16 fp16 HMMA, fp32 accum, D += A*B
__device__ __forceinline__ void mmaf16(float c[4], const uint32_t a[4],
                                       uint32_t b0, uint32_t b1) {
    asm volatile(
        "mma.sync.aligned.m16n8k16.row.col.f32.f16.f16.f32 "
        "{%0,%1,%2,%3}, {%4,%5,%6,%7}, {%8,%9}, {%0,%1,%2,%3};"
        : "+f"(c[0]), "+f"(c[1]), "+f"(c[2]), "+f"(c[3])
        : "r"(a[0]), "r"(a[1]), "r"(a[2]), "r"(a[3]), "r"(b0), "r"(b1));
}

#define LDSMX4(r, a) \
    asm volatile("ldmatrix.sync.aligned.m8n8.x4.shared.b16 {%0,%1,%2,%3}, [%4];" \
        : "=r"((r)[0]), "=r"((r)[1]), "=r"((r)[2]), "=r"((r)[3]) : "r"(a))

#define CPASYNC(dst, src) \
    asm volatile("cp.async.cg.shared.global [%0], [%1], 16;" :: "r"(dst), "l"(src))
#define CPCOMMIT() asm volatile("cp.async.commit_group;" ::: "memory")
#define CPWAIT(n)  asm volatile("cp.async.wait_group %0;" :: "n"(n) : "memory")

// ---------------- prep kernels (3 launches) ----------------------------------
__global__ void half_copy_bias(const float4* __restrict__ x, __half2* __restrict__ y,
                               int n4, const float* __restrict__ bq,
                               const float* __restrict__ bk,
                               const float* __restrict__ bv) {
    const int i = blockIdx.x * 256 + threadIdx.x;
    if (i < n4) {
        float4 v = x[i];
        y[2 * i]     = __floats2half2_rn(v.x, v.y);
        y[2 * i + 1] = __floats2half2_rn(v.z, v.w);
    }
    if (i < D_MODEL) {
        g_bqkv[i] = bq[i] * QK_SCALE;      // Q bias pre-scaled
        g_bqkv[i + 1024] = bk[i];
        g_bqkv[i + 2048] = bv[i];
    }
}

// fused transpose of Wo/W1/W2 (f32 [R][C] -> fp16 [C][R]), 1-D decoded grid
__global__ void transpose_all(const float* __restrict__ Wo,
                              const float* __restrict__ W1,
                              const float* __restrict__ W2) {
    __shared__ float t[32][33];
    int id = blockIdx.x;
    const float* src;
    __half* dst;
    int R, C, bx, by;
    if (id < 1024) {                       // Wo: 1024x1024
        src = Wo; dst = g_wo; R = D_MODEL; C = D_MODEL;
        bx = (id & 31) * 32; by = (id >> 5) * 32;
    } else if (id < 1024 + 4096) {         // W1: [1024,4096] -> [4096,1024]
        id -= 1024;
        src = W1; dst = g_w1; R = D_MODEL; C = FF;
        bx = (id & 127) * 32; by = (id >> 7) * 32;
    } else {                               // W2: [4096,1024] -> [1024,4096]
        id -= 1024 + 4096;
        src = W2; dst = g_w2; R = FF; C = D_MODEL;
        bx = (id & 31) * 32; by = (id >> 5) * 32;
    }
    const int tx = threadIdx.x, ty = threadIdx.y;
    {
        const int x = bx + tx;
#pragma unroll
        for (int j = 0; j < 32; j += 8)
            t[ty + j][tx] = src[(size_t)(by + ty + j) * C + x];
    }
    __syncthreads();
    {
        const int x = by + tx;
#pragma unroll
        for (int j = 0; j < 32; j += 8)
            dst[(size_t)(bx + ty + j) * R + x] = __float2half_rn(t[tx][ty + j]);
    }
}

// QKV weights [NH][1024][64] -> g_wqkv [3*NH*64][1024] fp16; Wq pre-scaled
__global__ void pack_qkvT3(const float* __restrict__ Wq, const float* __restrict__ Wk,
                           const float* __restrict__ Wv) {
    __shared__ float t[32][33];
    const int which = blockIdx.z >> 4;          // 0=q,1=k,2=v
    const int head = blockIdx.z & 15;
    const float* W = (which == 0) ? Wq : (which == 1) ? Wk : Wv;
    const float sc = (which == 0) ? (float)QK_SCALE : 1.0f;
    const float* s = W + (size_t)head * D_MODEL * DKH;
    __half* d = g_wqkv + ((size_t)which * 1024 + head * DKH) * D_MODEL;
    const int tx = threadIdx.x, ty = threadIdx.y;
    {
        const int x = blockIdx.x * 32 + tx;          // dk
#pragma unroll
        for (int j = 0; j < 32; j += 8)
            t[ty + j][tx] = s[(size_t)(blockIdx.y * 32 + ty + j) * DKH + x];
    }
    __syncthreads();
    {
        const int x = blockIdx.y * 32 + tx;          // d
#pragma unroll
        for (int j = 0; j < 32; j += 8)
            d[(size_t)(blockIdx.x * 32 + ty + j) * D_MODEL + x] =
                __float2half_rn(t[tx][ty + j] * sc);
    }
}

// ======================= FP16 GEMM (ldmatrix + cp.async 3-stage) =============
// C = A @ Bt^T + bias. A [M,K] half (lda), Bt [N,K] half (ldb).
// CTA 128x128, 128 threads, 4 warps 2x2, warp tile 64x64, k-chunk 32.
// 3-stage / 61440 B smem -> 2 CTAs/SM (validated local optimum; R7/R13/R15
// showed every perturbation of this envelope regresses; RF-bound at 194 regs).
// MODE 0: fp32 C.  MODE 1: QKV (Q fp16 pre-scaled / K fp16x2 / V^T fp16).
// MODE 2: half C (+ ReLU via RELU flag).
template <int MODE, bool RELU>
__global__ void __launch_bounds__(128)
gemm_f16(const __half* __restrict__ A, const __half* __restrict__ Bt,
         const float* __restrict__ bias, void* __restrict__ C,
         int K, int lda, int ldb, int ldc)
{
    constexpr int ASB = 80;                      // bytes per smem row
    constexpr uint32_t STAGE = 128 * ASB;        // 10240 B
    extern __shared__ uint32_t dsm[];
    const uint32_t saA = smem_u32(dsm);
    const uint32_t saB = saA + 3 * STAGE;

    const int tid = threadIdx.x, lane = tid & 31, wid = tid >> 5;
    const int wm = wid >> 1, wn = wid & 1;
    const int m0 = blockIdx.y * 128, n0 = blockIdx.x * 128;

    const __half* Ab = A + (size_t)m0 * lda;
    const __half* Bb = Bt + (size_t)n0 * ldb;

    float acc[4][8][4];
#pragma unroll
    for (int mt = 0; mt < 4; mt++)
#pragma unroll
        for (int nt = 0; nt < 8; nt++)
#pragma unroll
            for (int j = 0; j < 4; j++) acc[mt][nt][j] = 0.f;

    auto issue = [&](int ch) {
        const int st = ch % 3;
        const __half* Ac = Ab + ch * 32;
        const uint32_t ad = saA + st * STAGE;
#pragma unroll
        for (int i = 0; i < 4; i++) {
            const int idx = tid + i * 128;
            const int r = idx >> 2, q = idx & 3;
            CPASYNC(ad + r * ASB + q * 16, Ac + (size_t)r * lda + q * 8);
        }
        const __half* Bc = Bb + ch * 32;
        const uint32_t bd = saB + st * STAGE;
#pragma unroll
        for (int i = 0; i < 4; i++) {
            const int idx = tid + i * 128;
            const int r = idx >> 2, q = idx & 3;
            CPASYNC(bd + r * ASB + q * 16, Bc + (size_t)r * ldb + q * 8);
        }
    };

    auto compute = [&](int st) {
        const uint32_t aBase = saA + st * STAGE +
            (wm * 64 + (lane & 15)) * ASB + (lane >> 4) * 16;
        const uint32_t bBase = saB + st * STAGE +
            (wn * 64 + (lane & 7)) * ASB + (lane >> 3) * 16;
        uint32_t b[8][4];
#pragma unroll
        for (int nt = 0; nt < 8; nt++)
            LDSMX4(b[nt], bBase + nt * (8 * ASB));
#pragma unroll
        for (int sp = 0; sp < 2; sp++) {
            uint32_t a[4][4];
#pragma unroll
            for (int mt = 0; mt < 4; mt++)
                LDSMX4(a[mt], aBase + mt * (16 * ASB) + sp * 32);
#pragma unroll
            for (int mt = 0; mt < 4; mt++)
#pragma unroll
                for (int nt = 0; nt < 8; nt++)
                    mmaf16(acc[mt][nt], a[mt], b[nt][2 * sp], b[nt][2 * sp + 1]);
        }
    };

    const int NC = K / 32;
    issue(0); CPCOMMIT();
    issue(1); CPCOMMIT();
    for (int ch = 0; ch < NC - 1; ch++) {
        CPWAIT(1);
        __syncthreads();
        if (ch + 2 < NC) { issue(ch + 2); CPCOMMIT(); }
        compute(ch % 3);
    }
    CPWAIT(0);
    __syncthreads();
    compute((NC - 1) % 3);

    // epilogue
#pragma unroll
    for (int nt = 0; nt < 8; nt++) {
        const int col = n0 + wn * 64 + nt * 8 + (lane & 3) * 2;
        const float2 bv = *(const float2*)(bias + col);
#pragma unroll
        for (int mt = 0; mt < 4; mt++) {
            const int row = m0 + wm * 64 + mt * 16 + (lane >> 2);
            float2 v0, v1;
            v0.x = acc[mt][nt][0] + bv.x; v0.y = acc[mt][nt][1] + bv.y;
            v1.x = acc[mt][nt][2] + bv.x; v1.y = acc[mt][nt][3] + bv.y;
            if (RELU) {
                v0.x = fmaxf(v0.x, 0.f); v0.y = fmaxf(v0.y, 0.f);
                v1.x = fmaxf(v1.x, 0.f); v1.y = fmaxf(v1.y, 0.f);
            }
            if (MODE == 0) {
                float* Cf = (float*)C;
                *(float2*)(Cf + (size_t)row * ldc + col) = v0;
                *(float2*)(Cf + (size_t)(row + 8) * ldc + col) = v1;
            } else if (MODE == 2) {
                __half2* Ch = (__half2*)C;
                Ch[((size_t)row * ldc + col) >> 1]       = __floats2half2_rn(v0.x, v0.y);
                Ch[((size_t)(row + 8) * ldc + col) >> 1] = __floats2half2_rn(v1.x, v1.y);
            } else {
                if (n0 < 1024) {                       // Q: fp16 (pre-scaled)
                    __half2* qh = (__half2*)g_qh;
                    qh[((size_t)row * 1024 + col) >> 1]       = __floats2half2_rn(v0.x, v0.y);
                    qh[((size_t)(row + 8) * 1024 + col) >> 1] = __floats2half2_rn(v1.x, v1.y);
                } else if (n0 < 2048) {                // K: fp16 pairs [h][s][dk/2]
                    const int ck = col - 1024;
                    const int hh = ck >> 6, dk = ck & 63;
                    uint32_t* kb = g_kb + ((size_t)hh * S_LEN) * 32 + (dk >> 1);
                    kb[(size_t)row * 32]       = packh(v0.x, v0.y);
                    kb[(size_t)(row + 8) * 32] = packh(v1.x, v1.y);
                } else {                                // V: fp16 transposed [h][dk][s]
                    const int cv = col - 2048;
                    const int hh = cv >> 6, dk = cv & 63;
                    __half* vt = g_vt + ((size_t)(hh * 64 + dk)) * S_LEN;
                    vt[row]             = __float2half_rn(v0.x);
                    vt[S_LEN + row]     = __float2half_rn(v0.y);
                    vt[row + 8]         = __float2half_rn(v1.x);
                    vt[S_LEN + row + 8] = __float2half_rn(v1.y);
                }
            }
        }
    }
}

// ======================= fp16 flash attention (3-stage cp.async) ============
// grid (S/128, H), 256 threads, 8 warps each owning 16 Q rows.
// Q fp16 pre-scaled (direct 32-bit fragment loads). K fp16x2, V^T fp16,
// 3-stage cp.async. Softmax: pack f16x2 + ex2.approx.f16x2 == P A-fragment.
// Row sums via an extra mma with B == ones.
__global__ void __launch_bounds__(256, 2)
flash_f16()
{
    extern __shared__ uint32_t fsm[];
    uint32_t* Ks = fsm;                  // [3][64*36]
    uint32_t* Vs = fsm + 3 * 64 * 36;    // [3][64*36]
    const uint32_t ksA = smem_u32(Ks);
    const uint32_t vsA = smem_u32(Vs);
    constexpr uint32_t FST = 64 * 36 * 4;
    constexpr uint32_t ONES = 0x3C003C00u;   // fp16 (1.0, 1.0)

    const int tid = threadIdx.x, lane = tid & 31, wid = tid >> 5;
    const int h = blockIdx.y, qb = blockIdx.x * 128;
    const int row0 = wid * 16 + (lane >> 2);
    const int cq = lane & 3;

    const __half* Qg = g_qh + (size_t)qb * D_MODEL + h * DKH;
    const uint32_t* Kg = g_kb + ((size_t)h * S_LEN) * 32;
    const __half* Vg = g_vt + ((size_t)h * DKH) * S_LEN;

    uint32_t qa[4][4];
#pragma unroll
    for (int t = 0; t < 4; t++) {
        qa[t][0] = *(const uint32_t*)(Qg + (size_t)row0 * D_MODEL + 16 * t + 2 * cq);
        qa[t][1] = *(const uint32_t*)(Qg + (size_t)(row0 + 8) * D_MODEL + 16 * t + 2 * cq);
        qa[t][2] = *(const uint32_t*)(Qg + (size_t)row0 * D_MODEL + 16 * t + 8 + 2 * cq);
        qa[t][3] = *(const uint32_t*)(Qg + (size_t)(row0 + 8) * D_MODEL + 16 * t + 8 + 2 * cq);
    }

    auto issue = [&](int kt) {
        const int st = kt % 3;
        const uint32_t kd = ksA + st * FST;
        const uint32_t* kg = Kg + (size_t)(kt * 64) * 32;
#pragma unroll
        for (int j = 0; j < 2; j++) {
            const int idx = tid + j * 256;
            const int kv = idx >> 3, ch = idx & 7;
            CPASYNC(kd + (kv * 36 + ch * 4) * 4, kg + (size_t)kv * 32 + ch * 4);
        }
        const uint32_t vd = vsA + st * FST;
        const __half* vg = Vg + kt * 64;
#pragma unroll
        for (int j = 0; j < 2; j++) {
            const int idx = tid + j * 256;
            const int dk = idx >> 3, ch = idx & 7;
            CPASYNC(vd + (dk * 36 + ch * 4) * 4, vg + (size_t)dk * S_LEN + ch * 8);
        }
    };

    float oc[8][4];
#pragma unroll
    for (int dn = 0; dn < 8; dn++)
#pragma unroll
        for (int j = 0; j < 4; j++) oc[dn][j] = 0.f;
    float ocs[4] = {0.f, 0.f, 0.f, 0.f};

    constexpr int NT = S_LEN / 64;
    issue(0); CPCOMMIT();
    issue(1); CPCOMMIT();

    for (int kt = 0; kt < NT; kt++) {
        if (kt < NT - 1) { CPWAIT(1); } else { CPWAIT(0); }
        __syncthreads();
        if (kt + 2 < NT) { issue(kt + 2); CPCOMMIT(); }

        const int st = kt % 3;
        const uint32_t* Kp = Ks + st * (64 * 36);
        const uint32_t* Vp = Vs + st * (64 * 36);

        float sc[8][4];
#pragma unroll
        for (int nt = 0; nt < 8; nt++)
#pragma unroll
            for (int j = 0; j < 4; j++) sc[nt][j] = 0.f;
#pragma unroll
        for (int t = 0; t < 4; t++) {
#pragma unroll
            for (int nt = 0; nt < 8; nt++) {
                const uint32_t* p = &Kp[(nt * 8 + (lane >> 2)) * 36 + 8 * t + cq];
                mmaf16(sc[nt], qa[t], p[0], p[4]);
            }
        }

        uint32_t pa[4][4];
#pragma unroll
        for (int nt = 0; nt < 8; nt++) {
            const int u = nt >> 1, hi = (nt & 1) * 2;
            pa[u][hi]     = ex2h2(packh(sc[nt][0], sc[nt][1]));
            pa[u][hi + 1] = ex2h2(packh(sc[nt][2], sc[nt][3]));
        }

#pragma unroll
        for (int u = 0; u < 4; u++) {
            mmaf16(ocs, pa[u], ONES, ONES);
#pragma unroll
            for (int dn = 0; dn < 8; dn++) {
                const uint32_t* p = &Vp[(dn * 8 + (lane >> 2)) * 36 + 8 * u + cq];
                mmaf16(oc[dn], pa[u], p[0], p[4]);
            }
        }
        // next iteration's top-of-loop barrier orders the stage overwrite.
    }

    const float inv0 = 1.f / ocs[0];
    const float inv1 = 1.f / ocs[2];
    __half* o0 = g_cch + (size_t)(qb + row0) * D_MODEL + h * DKH;
    __half* o1 = g_cch + (size_t)(qb + row0 + 8) * D_MODEL + h * DKH;
#pragma unroll
    for (int dn = 0; dn < 8; dn++) {
        const int col = dn * 8 + 2 * cq;
        *(__half2*)(o0 + col) = __floats2half2_rn(oc[dn][0] * inv0, oc[dn][1] * inv0);
        *(__half2*)(o1 + col) = __floats2half2_rn(oc[dn][2] * inv1, oc[dn][3] * inv1);
    }
}

// ---------------- layernorm with residual: out = LN(a + b), b fp16 ---------
__global__ void ln_residual_kernel(const float* __restrict__ a,
                                   const __half* __restrict__ b,
                                   const float* __restrict__ gw,
                                   const float* __restrict__ bw,
                                   float* __restrict__ out,
                                   __half* __restrict__ out_h)
{
    const int row = blockIdx.x;
    const int t = threadIdx.x;
    const float* ar = a + (size_t)row * D_MODEL;
    const __half* br = b + (size_t)row * D_MODEL;

    float v[4];
    float s1 = 0.f, s2 = 0.f;
#pragma unroll
    for (int i = 0; i < 4; i++) {
        const int c = t + i * 256;
        const float x = ar[c] + __half2float(br[c]);
        v[i] = x;
        s1 += x;
        s2 += x * x;
    }
#pragma unroll
    for (int o = 16; o; o >>= 1) {
        s1 += __shfl_xor_sync(0xffffffffu, s1, o);
        s2 += __shfl_xor_sync(0xffffffffu, s2, o);
    }
    __shared__ float r1[8], r2[8];
    __shared__ float mu_s, rs_s;
    if ((t & 31) == 0) { r1[t >> 5] = s1; r2[t >> 5] = s2; }
    __syncthreads();
    if (t == 0) {
        float a1 = 0.f, a2 = 0.f;
#pragma unroll
        for (int i = 0; i < 8; i++) { a1 += r1[i]; a2 += r2[i]; }
        const float mu = a1 * (1.f / D_MODEL);
        const float var = a2 * (1.f / D_MODEL) - mu * mu;
        mu_s = mu;
        rs_s = rsqrtf(var + 1e-5f);
    }
    __syncthreads();
    const float mu = mu_s, rs = rs_s;
    float* orow = out + (size_t)row * D_MODEL;
    __half* hrow = out_h ? out_h + (size_t)row * D_MODEL : nullptr;
#pragma unroll
    for (int i = 0; i < 4; i++) {
        const int c = t + i * 256;
        const float y = (v[i] - mu) * rs * gw[c] + bw[c];
        orow[c] = y;
        if (out_h) hrow[c] = __float2half_rn(y);
    }
}

// ---------------- launch ----------------------------------------------------
extern "C" void kernel_launch(void* const* d_in, const int* in_sizes, int n_in,
                              void* d_out, int out_size)
{
    (void)in_sizes; (void)n_in; (void)out_size;
    const float* src   = (const float*)d_in[0];
    const float* Wq    = (const float*)d_in[1];
    const float* bq    = (const float*)d_in[2];
    const float* Wk    = (const float*)d_in[3];
    const float* bk    = (const float*)d_in[4];
    const float* Wv    = (const float*)d_in[5];
    const float* bv    = (const float*)d_in[6];
    const float* Wo    = (const float*)d_in[7];
    const float* bo    = (const float*)d_in[8];
    const float* ln1_g = (const float*)d_in[9];
    const float* ln1_b = (const float*)d_in[10];
    const float* W1    = (const float*)d_in[11];
    const float* b1    = (const float*)d_in[12];
    const float* W2    = (const float*)d_in[13];
    const float* b2    = (const float*)d_in[14];
    const float* ln2_g = (const float*)d_in[15];
    const float* ln2_b = (const float*)d_in[16];
    float* out = (float*)d_out;

    void *psrch, *pwo, *pw1, *pw2, *pcch, *ptmph, *px1, *px1h, *ph1h, *pwqkv, *pbqkv;
    cudaGetSymbolAddress(&psrch, g_srch);
    cudaGetSymbolAddress(&pwqkv, g_wqkv);
    cudaGetSymbolAddress(&pbqkv, g_bqkv);
    cudaGetSymbolAddress(&pwo, g_wo);
    cudaGetSymbolAddress(&pw1, g_w1);
    cudaGetSymbolAddress(&pw2, g_w2);
    cudaGetSymbolAddress(&pcch, g_cch);
    cudaGetSymbolAddress(&ptmph, g_tmph);
    cudaGetSymbolAddress(&px1, g_x1);
    cudaGetSymbolAddress(&px1h, g_x1h);
    cudaGetSymbolAddress(&ph1h, g_h1h);

    const int GSMEM = 6 * 128 * 80;              // 61440 B -> 2 CTAs/SM
    const int FSMEM = 6 * 64 * 36 * 4;           // 55296 B -> 2 CTAs/SM
    cudaFuncSetAttribute(gemm_f16<2, false>,
                         cudaFuncAttributeMaxDynamicSharedMemorySize, GSMEM);
    cudaFuncSetAttribute(gemm_f16<2, true>,
                         cudaFuncAttributeMaxDynamicSharedMemorySize, GSMEM);
    cudaFuncSetAttribute(gemm_f16<1, false>,
                         cudaFuncAttributeMaxDynamicSharedMemorySize, GSMEM);
    cudaFuncSetAttribute(flash_f16,
                         cudaFuncAttributeMaxDynamicSharedMemorySize, FSMEM);

    // ---- prep: 3 launches ----
    half_copy_bias<<<(S_LEN * D_MODEL / 4 + 255) / 256, 256>>>(
        (const float4*)src, (__half2*)psrch, S_LEN * D_MODEL / 4, bq, bk, bv);
    transpose_all<<<1024 + 4096 + 4096, dim3(32, 8)>>>(Wo, W1, W2);
    pack_qkvT3<<<dim3(2, 32, 48), dim3(32, 8)>>>(Wq, Wk, Wv);

    // ---- fused QKV: [4096,1024] x [1024,3072]; writes g_qh/g_kb/g_vt ----
    gemm_f16<1, false><<<dim3(3072 / 128, S_LEN / 128), 128, GSMEM>>>(
        (const __half*)psrch, (const __half*)pwqkv, (const float*)pbqkv,
        nullptr, D_MODEL, D_MODEL, D_MODEL, 0);

    // ---- attention -> g_cch [S, H*DK] fp16 ----
    flash_f16<<<dim3(S_LEN / 128, NH), 256, FSMEM>>>();

    // ---- output projection [4096,1024] x [1024,1024] -> fp16 tmp ----
    gemm_f16<2, false><<<dim3(D_MODEL / 128, S_LEN / 128), 128, GSMEM>>>(
        (const __half*)pcch, (const __half*)pwo, bo, ptmph,
        D_MODEL, D_MODEL, D_MODEL, D_MODEL);
    // x1 = LN(src + attn_out): fp32 + fp16 copy
    ln_residual_kernel<<<S_LEN, 256>>>(src, (const __half*)ptmph, ln1_g, ln1_b,
                                       (float*)px1, (__half*)px1h);

    // ---- FFN up: relu(x1 @ W1 + b1) -> fp16 h1 ----
    gemm_f16<2, true><<<dim3(FF / 128, S_LEN / 128), 128, GSMEM>>>(
        (const __half*)px1h, (const __half*)pw1, b1, ph1h,
        D_MODEL, D_MODEL, D_MODEL, FF);
    // ---- FFN down: h1 @ W2 + b2 -> fp16 tmp ----
    gemm_f16<2, false><<<dim3(D_MODEL / 128, S_LEN / 128), 128, GSMEM>>>(
        (const __half*)ph1h, (const __half*)pw2, b2, ptmph,
        FF, FF, FF, D_MODEL);
    // out = LN(x1 + ffn), fp32 output
    ln_residual_kernel<<<S_LEN, 256>>>((const float*)px1, (const __half*)ptmph,
                                       ln2_g, ln2_b, out, nullptr);
}